// round 12
// baseline (speedup 1.0000x reference)
#include <cuda_runtime.h>
#include <cstdint>

// Problem constants
#define BB 8
#define TT 128
#define NTHREADS 512

// Output layout (float32, concatenated): outputs[8,128,256], seq_lengths[8],
// hidden[1,8,256], attn[8,128,128]
#define SEQ_OFF     262144
#define HID_OFF     262152
#define ATTN_OFF    264200

// Device scratch
__device__ float g_xw1[1024 * 512];          // x @ W1[:, :E]^T + b1
__device__ float g_wx[1024 * 1024];          // x @ Wih^T
__device__ float g_ep[BB][2][16][128];       // energy partials, double-buffered
__device__ float g_h[BB][2][256];            // replicated h, double-buffered
__device__ unsigned g_fep[BB][TT];           // per-step EP flags (release/acquire)
__device__ unsigned g_fh[BB][TT];            // per-step h flags

// ---------------- SMEM layout (float offsets); B = batch slot 0/1 ----------------
#define OFF_W1H   0        // [32][256]  shared across batches
#define OFF_WHH   8192     // [64][256]  shared
#define OFF_WX    24576    // [2][128][68] per-batch (stride 8704)
#define OFF_BIAS  41984    // [64] shared
#define OFF_HPST  42048    // [2][32]
#define OFF_HWST  42112    // [2][64]
#define OFF_WB    42240    // [2][128]
#define OFF_GFIN  42496    // [2][64]
#define OFF_CST   42624    // [2][16]
#define OFF_SRED  42656    // [2][16]
#define SMEM_FLOATS 42688
#define SMEM_BYTES (SMEM_FLOATS * 4)   // 170752 B

// ---------------- helpers ----------------
__device__ __forceinline__ float ldcv(const float* p) {
    float v; asm volatile("ld.global.cv.f32 %0, [%1];" : "=f"(v) : "l"(p)); return v;
}
__device__ __forceinline__ float4 ldcv4(const float* p) {
    float4 v;
    asm volatile("ld.global.cv.v4.f32 {%0,%1,%2,%3}, [%4];"
                 : "=f"(v.x), "=f"(v.y), "=f"(v.z), "=f"(v.w) : "l"(p));
    return v;
}
__device__ __forceinline__ void red_rel(unsigned* p) {
    asm volatile("red.add.release.gpu.u32 [%0], 1;" :: "l"(p) : "memory");
}
__device__ __forceinline__ unsigned ld_acq(const unsigned* p) {
    unsigned v;
    asm volatile("ld.acquire.gpu.u32 %0, [%1];" : "=r"(v) : "l"(p) : "memory");
    return v;
}
__device__ __forceinline__ void spin16(const unsigned* p) {
    while (ld_acq(p) < 16u) {}
}
__device__ __forceinline__ float wsum(float v) {
    #pragma unroll
    for (int o = 16; o > 0; o >>= 1) v += __shfl_xor_sync(0xffffffffu, v, o);
    return v;
}
// ---- 2-MUFU tanh: e = exp(2x); (e-1)/(e+1). ~1e-6 accurate ----
__device__ __forceinline__ float tanh_m(float x) {
    x = fminf(fmaxf(x, -9.f), 9.f);
    float e = __expf(2.f * x);
    return __fdividef(e - 1.f, e + 1.f);
}
__device__ __forceinline__ float sigmoid_m(float x) {
    return __fdividef(1.f, 1.f + __expf(-x));
}

// ---------------- flag zeroing (runs first every launch/replay) ----------------
__global__ void zero_flags() {
    int i = blockIdx.x * blockDim.x + threadIdx.x;
    if (i < BB * TT) {
        (&g_fep[0][0])[i] = 0u;
        (&g_fh[0][0])[i]  = 0u;
    }
}

// ---------------- precompute GEMMs ----------------
template <int NOUT, bool HASB>
__global__ void nt_gemm(const float* __restrict__ X, const float* __restrict__ W,
                        const float* __restrict__ bias, float* __restrict__ outp) {
    __shared__ float As[64][33];
    __shared__ float Bs[64][33];
    const int m0 = blockIdx.x * 64, n0 = blockIdx.y * 64;
    const int tx = threadIdx.x, ty = threadIdx.y;
    const int tid = ty * 16 + tx;
    float acc[4][4] = {};
    for (int kt = 0; kt < 256; kt += 32) {
        for (int idx = tid; idx < 64 * 32; idx += 256) {
            int rr = idx >> 5, kk = idx & 31;
            As[rr][kk] = X[(m0 + rr) * 256 + kt + kk];
            Bs[rr][kk] = W[(size_t)(n0 + rr) * 256 + kt + kk];
        }
        __syncthreads();
        #pragma unroll
        for (int kk = 0; kk < 32; kk++) {
            float a[4], bv[4];
            #pragma unroll
            for (int i = 0; i < 4; i++) { a[i] = As[ty*4+i][kk]; bv[i] = Bs[tx*4+i][kk]; }
            #pragma unroll
            for (int i = 0; i < 4; i++)
                #pragma unroll
                for (int j = 0; j < 4; j++) acc[i][j] += a[i] * bv[j];
        }
        __syncthreads();
    }
    #pragma unroll
    for (int i = 0; i < 4; i++)
        #pragma unroll
        for (int j = 0; j < 4; j++) {
            int n = n0 + tx*4 + j;
            float v = acc[i][j];
            if (HASB) v += bias[n];
            outp[(size_t)(m0 + ty*4 + i) * NOUT + n] = v;
        }
}

__global__ void xw1_gemm(const float* __restrict__ X, const float* __restrict__ W1,
                         const float* __restrict__ b1) {
    __shared__ float As[64][33];
    __shared__ float Bs[64][33];
    const int m0 = blockIdx.x * 64, n0 = blockIdx.y * 64;
    const int tx = threadIdx.x, ty = threadIdx.y;
    const int tid = ty * 16 + tx;
    float acc[4][4] = {};
    for (int kt = 0; kt < 256; kt += 32) {
        for (int idx = tid; idx < 64 * 32; idx += 256) {
            int rr = idx >> 5, kk = idx & 31;
            As[rr][kk] = X[(m0 + rr) * 256 + kt + kk];
            Bs[rr][kk] = W1[(size_t)(n0 + rr) * 512 + kt + kk];
        }
        __syncthreads();
        #pragma unroll
        for (int kk = 0; kk < 32; kk++) {
            float a[4], bv[4];
            #pragma unroll
            for (int i = 0; i < 4; i++) { a[i] = As[ty*4+i][kk]; bv[i] = Bs[tx*4+i][kk]; }
            #pragma unroll
            for (int i = 0; i < 4; i++)
                #pragma unroll
                for (int j = 0; j < 4; j++) acc[i][j] += a[i] * bv[j];
        }
        __syncthreads();
    }
    #pragma unroll
    for (int i = 0; i < 4; i++)
        #pragma unroll
        for (int j = 0; j < 4; j++) {
            int n = n0 + tx*4 + j;
            g_xw1[(size_t)(m0 + ty*4 + i) * 512 + n] = acc[i][j] + b1[n];
        }
}

// ---------------- persistent recurrence: 64 CTAs, 2 batches/CTA interleaved ----------------
__global__ void __launch_bounds__(NTHREADS, 1)
lstm_attn(const float* __restrict__ x, const int* __restrict__ seqlen,
          const float* __restrict__ W1, const float* __restrict__ W2,
          const float* __restrict__ b2w, const float* __restrict__ Whh,
          const float* __restrict__ bih, const float* __restrict__ bhh,
          float* __restrict__ out) {
    extern __shared__ float sm[];
    const int tid = threadIdx.x;
    const int w = tid >> 5, lane = tid & 31;
    const int r = blockIdx.x & 15;
    const int p = blockIdx.x >> 4;              // pair id 0..3
    const int bb[2] = { p, p + 4 };
    const int lenv[2] = { seqlen[bb[0]], seqlen[bb[1]] };
    const float b2v = b2w[0];

    // ---- prologue: weight slices (shared) + per-batch Wx ----
    for (int idx = tid; idx < 32 * 256; idx += NTHREADS) {          // W1 h-cols, k rows [32r,32r+32)
        int row = idx >> 8, d = idx & 255;
        sm[OFF_W1H + idx] = W1[(size_t)(32 * r + row) * 512 + 256 + d];
    }
    for (int idx = tid; idx < 64 * 256; idx += NTHREADS) {          // Whh rows for my gates
        int q = idx >> 8, d = idx & 255;
        int gate = q >> 4, i = q & 15;
        sm[OFF_WHH + idx] = Whh[(size_t)(gate * 256 + 16 * r + i) * 256 + d];
    }
    #pragma unroll
    for (int B = 0; B < 2; B++)
        for (int idx = tid; idx < 128 * 64; idx += NTHREADS) {      // Wx[j][my 64 rows], pitch 68
            int j = idx >> 6, q = idx & 63;
            sm[OFF_WX + B * 8704 + j * 68 + q] =
                g_wx[(size_t)(bb[B] * 128 + j) * 1024 + ((q >> 4) << 8) + 16 * r + (q & 15)];
        }
    if (tid < 64) {
        int gate = tid >> 4, i = tid & 15;
        int row = gate * 256 + 16 * r + i;
        sm[OFF_BIAS + tid] = bih[row] + bhh[row];
    }
    if (tid < 64) sm[OFF_HPST + tid] = 0.f;            // both batches: t=0 hproj = 0
    if (tid < 32) sm[OFF_CST + tid] = 0.f;
    if (r == 0 && tid == 0) {
        out[SEQ_OFF + bb[0]] = (float)lenv[0];
        out[SEQ_OFF + bb[1]] = (float)lenv[1];
    }

    // per-thread loop-invariant registers
    const int jE = tid >> 2, qE = tid & 3;
    float xwr[2][8], w2r[8];
    {
        const float* w2s = W2 + 32 * r + qE * 8;
        #pragma unroll
        for (int i = 0; i < 8; i++) w2r[i] = w2s[i];
        #pragma unroll
        for (int B = 0; B < 2; B++) {
            const float* src = g_xw1 + (size_t)(bb[B] * 128 + jE) * 512 + 32 * r + qE * 8;
            #pragma unroll
            for (int i = 0; i < 8; i++) xwr[B][i] = src[i];
        }
    }
    __syncthreads();

    for (int t = 0; t < TT; t++) {
        const int slot = t & 1;

        // ======== EP phases: b1 then b2 (each hides the other's L2 traffic) ========
        #pragma unroll
        for (int B = 0; B < 2; B++) {
            const int b = bb[B];
            float4 h0 = make_float4(0.f, 0.f, 0.f, 0.f), h1 = h0;
            if (t > 0) {
                spin16(&g_fh[b][t - 1]);
                h0 = ldcv4(&g_h[b][slot][lane * 8]);
                h1 = ldcv4(&g_h[b][slot][lane * 8 + 4]);
                #pragma unroll
                for (int rr = 0; rr < 2; rr++) {       // hproj: 2 rows/warp
                    int row = w * 2 + rr;
                    const float* wr = sm + OFF_W1H + row * 256;
                    float4 a0 = *(const float4*)(wr + lane * 8);
                    float4 a1 = *(const float4*)(wr + lane * 8 + 4);
                    float acc = a0.x*h0.x + a0.y*h0.y + a0.z*h0.z + a0.w*h0.w
                              + a1.x*h1.x + a1.y*h1.y + a1.z*h1.z + a1.w*h1.w;
                    acc = wsum(acc);
                    if (lane == 0) sm[OFF_HPST + B * 32 + row] = acc;
                }
            }
            __syncthreads();   // HPST[B] ready

            // energy partials (8 tanh/thread) -> g_ep
            {
                const float4* hp4 = (const float4*)(sm + OFF_HPST + B * 32 + qE * 8);
                float4 hpa = hp4[0], hpb = hp4[1];
                const float hp[8] = {hpa.x, hpa.y, hpa.z, hpa.w, hpb.x, hpb.y, hpb.z, hpb.w};
                float acc = 0.f;
                #pragma unroll
                for (int i = 0; i < 8; i++)
                    acc = fmaf(tanh_m(xwr[B][i] + hp[i]), w2r[i], acc);
                acc += __shfl_xor_sync(0xffffffffu, acc, 1);
                acc += __shfl_xor_sync(0xffffffffu, acc, 2);
                if (qE == 0) g_ep[b][slot][r][jE] = acc;
            }
            __syncthreads();   // EP stores issued
            if (tid == 0) red_rel(&g_fep[b][t]);

            // hWhh (4 rows/warp) — off the publish path, hidden under round trips
            #pragma unroll
            for (int rr = 0; rr < 4; rr++) {
                int row = w * 4 + rr;
                const float* wr = sm + OFF_WHH + row * 256;
                float4 a0 = *(const float4*)(wr + lane * 8);
                float4 a1 = *(const float4*)(wr + lane * 8 + 4);
                float acc = a0.x*h0.x + a0.y*h0.y + a0.z*h0.z + a0.w*h0.w
                          + a1.x*h1.x + a1.y*h1.y + a1.z*h1.z + a1.w*h1.w;
                acc = wsum(acc);
                if (lane == 0) sm[OFF_HWST + B * 64 + row] = acc;
            }
        }

        // ======== GATE phases: b1 then b2 ========
        #pragma unroll
        for (int B = 0; B < 2; B++) {
            const int b = bb[B];
            const bool active = t < lenv[B];

            spin16(&g_fep[b][t]);
            float ex = 0.f;
            {
                const float* epb = &g_ep[b][slot][0][0];
                float s = ldcv(epb + (4*qE + 0) * 128 + jE) + ldcv(epb + (4*qE + 1) * 128 + jE)
                        + ldcv(epb + (4*qE + 2) * 128 + jE) + ldcv(epb + (4*qE + 3) * 128 + jE);
                s += __shfl_xor_sync(0xffffffffu, s, 1);
                s += __shfl_xor_sync(0xffffffffu, s, 2);
                if (qE == 0)
                    ex = (jE < lenv[B]) ? __expf(tanh_m(s + b2v)) : 0.f;  // energies in [-1,1]
            }
            float wp = wsum(ex);
            if (lane == 0) sm[OFF_SRED + B * 16 + w] = wp;
            __syncthreads();   // SRED[B] ready (also publishes HWST[B])
            {
                const float4* sr = (const float4*)(sm + OFF_SRED + B * 16);
                float4 a = sr[0], c = sr[1], d = sr[2], e4 = sr[3];
                float S = (a.x+a.y+a.z+a.w) + (c.x+c.y+c.z+c.w)
                        + (d.x+d.y+d.z+d.w) + (e4.x+e4.y+e4.z+e4.w);
                float Sinv = __fdividef(1.f, S);
                if (qE == 0) {
                    float wv = active ? ex * Sinv : 0.f;
                    sm[OFF_WB + B * 128 + jE] = wv;
                    if ((jE >> 3) == r)
                        out[ATTN_OFF + (size_t)(b * 128 + t) * 128 + jE] = wv;
                }
            }
            __syncthreads();   // WB[B] ready

            // gates from Wx: row q = tid>>3, jq = tid&7
            {
                int q = tid >> 3, jq = tid & 7;
                const float* wx = sm + OFF_WX + B * 8704 + q;
                const float* wb = sm + OFF_WB + B * 128;
                float acc = 0.f;
                #pragma unroll
                for (int jj = 0; jj < 16; jj++) {
                    int j = jq + 8 * jj;
                    acc = fmaf(wb[j], wx[j * 68], acc);
                }
                acc += __shfl_xor_sync(0xffffffffu, acc, 1);
                acc += __shfl_xor_sync(0xffffffffu, acc, 2);
                acc += __shfl_xor_sync(0xffffffffu, acc, 4);
                if (jq == 0) {
                    acc += sm[OFF_HWST + B * 64 + q] + sm[OFF_BIAS + q];
                    sm[OFF_GFIN + B * 64 + q] = ((q >> 4) == 2) ? tanh_m(acc) : sigmoid_m(acc);
                }
            }
            __syncthreads();   // GFIN[B] ready

            // LSTM update (warp 0); publish h(t+1)
            if (tid < 16) {
                const float* gf = sm + OFF_GFIN + B * 64;
                float c = gf[16 + tid] * sm[OFF_CST + B * 16 + tid] + gf[tid] * gf[32 + tid];
                sm[OFF_CST + B * 16 + tid] = c;
                float hn = gf[48 + tid] * tanh_m(c);
                out[(size_t)(b * 128 + t) * 256 + 16 * r + tid] = active ? hn : 0.f;
                if (t == lenv[B] - 1) out[HID_OFF + b * 256 + 16 * r + tid] = hn;
                if (t < TT - 1) g_h[b][(t + 1) & 1][16 * r + tid] = hn;
                __syncwarp(0x0000ffffu);
                if (tid == 0 && t < TT - 1) red_rel(&g_fh[b][t]);
            }
            // no trailing bar: next phase gates on its own spins
        }
    }
}

// ---------------- host launch ----------------
extern "C" void kernel_launch(void* const* d_in, const int* in_sizes, int n_in,
                              void* d_out, int out_size) {
    const float* x   = (const float*)d_in[0];
    const int*   sl  = (const int*)  d_in[1];
    const float* W1  = (const float*)d_in[2];
    const float* b1  = (const float*)d_in[3];
    const float* W2  = (const float*)d_in[4];
    const float* b2  = (const float*)d_in[5];
    const float* Wih = (const float*)d_in[6];
    const float* Whh = (const float*)d_in[7];
    const float* bih = (const float*)d_in[8];
    const float* bhh = (const float*)d_in[9];
    float* out = (float*)d_out;

    zero_flags<<<2, 512>>>();
    xw1_gemm<<<dim3(16, 8), dim3(16, 16)>>>(x, W1, b1);
    {
        float* gwx;
        cudaGetSymbolAddress((void**)&gwx, g_wx);
        nt_gemm<1024, false><<<dim3(16, 16), dim3(16, 16)>>>(x, Wih, nullptr, gwx);
    }

    cudaFuncSetAttribute(lstm_attn, cudaFuncAttributeMaxDynamicSharedMemorySize, SMEM_BYTES);
    lstm_attn<<<BB * 8, NTHREADS, SMEM_BYTES>>>(x, sl, W1, W2, b2, Whh, bih, bhh, out);
}

// round 13
// speedup vs baseline: 1.3724x; 1.3724x over previous
#include <cuda_runtime.h>
#include <cstdint>

// Problem constants
#define BB 8
#define TT 128
#define NTHREADS 512

// Output layout (float32, concatenated): outputs[8,128,256], seq_lengths[8],
// hidden[1,8,256], attn[8,128,128]
#define SEQ_OFF     262144
#define HID_OFF     262152
#define ATTN_OFF    264200

// Device scratch
__device__ float g_xw1[1024 * 512];          // x @ W1[:, :E]^T + b1
__device__ float g_wx[1024 * 1024];          // x @ Wih^T
__device__ float g_ep[BB][2][16][128];       // energy partials, double-buffered
__device__ float g_h[BB][2][256];            // replicated h, double-buffered
__device__ unsigned g_fep[BB][TT];           // per-step EP flags (release/acquire)
__device__ unsigned g_fh[BB][TT];            // per-step h flags

// ---------------- SMEM layout (float offsets); G = batch group 0/1 ----------------
#define OFF_W1H   0        // [32][256]  shared across groups (same r slice)
#define OFF_WHH   8192     // [64][256]  shared
#define OFF_WX    24576    // [2][128][68] per-group (stride 8704)
#define OFF_BIAS  41984    // [64] shared
#define OFF_HPST  42048    // [2][32]
#define OFF_HWST  42112    // [2][64]
#define OFF_WB    42240    // [2][128]
#define OFF_GFIN  42496    // [2][64]
#define OFF_CST   42624    // [2][16]
#define OFF_SRED  42656    // [2][8]
#define SMEM_FLOATS 42688
#define SMEM_BYTES (SMEM_FLOATS * 4)   // 170752 B

// ---------------- helpers ----------------
__device__ __forceinline__ float ldcv(const float* p) {
    float v; asm volatile("ld.global.cv.f32 %0, [%1];" : "=f"(v) : "l"(p)); return v;
}
__device__ __forceinline__ float4 ldcv4(const float* p) {
    float4 v;
    asm volatile("ld.global.cv.v4.f32 {%0,%1,%2,%3}, [%4];"
                 : "=f"(v.x), "=f"(v.y), "=f"(v.z), "=f"(v.w) : "l"(p));
    return v;
}
__device__ __forceinline__ void red_rel(unsigned* p) {
    asm volatile("red.add.release.gpu.u32 [%0], 1;" :: "l"(p) : "memory");
}
__device__ __forceinline__ unsigned ld_acq(const unsigned* p) {
    unsigned v;
    asm volatile("ld.acquire.gpu.u32 %0, [%1];" : "=r"(v) : "l"(p) : "memory");
    return v;
}
__device__ __forceinline__ void spin16(const unsigned* p) {
    while (ld_acq(p) < 16u) {}
}
// named barrier: 256 threads of one group (id 1 or 2)
__device__ __forceinline__ void gbar(int id) {
    asm volatile("bar.sync %0, 256;" :: "r"(id) : "memory");
}
__device__ __forceinline__ float wsum(float v) {
    #pragma unroll
    for (int o = 16; o > 0; o >>= 1) v += __shfl_xor_sync(0xffffffffu, v, o);
    return v;
}
// ---- 2-MUFU tanh: e = exp(2x); (e-1)/(e+1). ~1e-6 accurate ----
__device__ __forceinline__ float tanh_m(float x) {
    x = fminf(fmaxf(x, -9.f), 9.f);
    float e = __expf(2.f * x);
    return __fdividef(e - 1.f, e + 1.f);
}
__device__ __forceinline__ float sigmoid_m(float x) {
    return __fdividef(1.f, 1.f + __expf(-x));
}

// ---------------- flag zeroing (runs first every launch/replay) ----------------
__global__ void zero_flags() {
    int i = blockIdx.x * blockDim.x + threadIdx.x;
    if (i < BB * TT) {
        (&g_fep[0][0])[i] = 0u;
        (&g_fh[0][0])[i]  = 0u;
    }
}

// ---------------- precompute GEMMs ----------------
template <int NOUT, bool HASB>
__global__ void nt_gemm(const float* __restrict__ X, const float* __restrict__ W,
                        const float* __restrict__ bias, float* __restrict__ outp) {
    __shared__ float As[64][33];
    __shared__ float Bs[64][33];
    const int m0 = blockIdx.x * 64, n0 = blockIdx.y * 64;
    const int tx = threadIdx.x, ty = threadIdx.y;
    const int tid = ty * 16 + tx;
    float acc[4][4] = {};
    for (int kt = 0; kt < 256; kt += 32) {
        for (int idx = tid; idx < 64 * 32; idx += 256) {
            int rr = idx >> 5, kk = idx & 31;
            As[rr][kk] = X[(m0 + rr) * 256 + kt + kk];
            Bs[rr][kk] = W[(size_t)(n0 + rr) * 256 + kt + kk];
        }
        __syncthreads();
        #pragma unroll
        for (int kk = 0; kk < 32; kk++) {
            float a[4], bv[4];
            #pragma unroll
            for (int i = 0; i < 4; i++) { a[i] = As[ty*4+i][kk]; bv[i] = Bs[tx*4+i][kk]; }
            #pragma unroll
            for (int i = 0; i < 4; i++)
                #pragma unroll
                for (int j = 0; j < 4; j++) acc[i][j] += a[i] * bv[j];
        }
        __syncthreads();
    }
    #pragma unroll
    for (int i = 0; i < 4; i++)
        #pragma unroll
        for (int j = 0; j < 4; j++) {
            int n = n0 + tx*4 + j;
            float v = acc[i][j];
            if (HASB) v += bias[n];
            outp[(size_t)(m0 + ty*4 + i) * NOUT + n] = v;
        }
}

__global__ void xw1_gemm(const float* __restrict__ X, const float* __restrict__ W1,
                         const float* __restrict__ b1) {
    __shared__ float As[64][33];
    __shared__ float Bs[64][33];
    const int m0 = blockIdx.x * 64, n0 = blockIdx.y * 64;
    const int tx = threadIdx.x, ty = threadIdx.y;
    const int tid = ty * 16 + tx;
    float acc[4][4] = {};
    for (int kt = 0; kt < 256; kt += 32) {
        for (int idx = tid; idx < 64 * 32; idx += 256) {
            int rr = idx >> 5, kk = idx & 31;
            As[rr][kk] = X[(m0 + rr) * 256 + kt + kk];
            Bs[rr][kk] = W1[(size_t)(n0 + rr) * 512 + kt + kk];
        }
        __syncthreads();
        #pragma unroll
        for (int kk = 0; kk < 32; kk++) {
            float a[4], bv[4];
            #pragma unroll
            for (int i = 0; i < 4; i++) { a[i] = As[ty*4+i][kk]; bv[i] = Bs[tx*4+i][kk]; }
            #pragma unroll
            for (int i = 0; i < 4; i++)
                #pragma unroll
                for (int j = 0; j < 4; j++) acc[i][j] += a[i] * bv[j];
        }
        __syncthreads();
    }
    #pragma unroll
    for (int i = 0; i < 4; i++)
        #pragma unroll
        for (int j = 0; j < 4; j++) {
            int n = n0 + tx*4 + j;
            g_xw1[(size_t)(m0 + ty*4 + i) * 512 + n] = acc[i][j] + b1[n];
        }
}

// ---------------- persistent recurrence: 64 CTAs, 2 warp-specialized batch groups ----------------
__global__ void __launch_bounds__(NTHREADS, 1)
lstm_attn(const float* __restrict__ x, const int* __restrict__ seqlen,
          const float* __restrict__ W1, const float* __restrict__ W2,
          const float* __restrict__ b2w, const float* __restrict__ Whh,
          const float* __restrict__ bih, const float* __restrict__ bhh,
          float* __restrict__ out) {
    extern __shared__ float sm[];
    const int tid = threadIdx.x;
    const int r = blockIdx.x & 15;
    const int p = blockIdx.x >> 4;             // pair id 0..3
    const int G = tid >> 8;                    // batch group 0/1 (warps 0-7 | 8-15)
    const int tid2 = tid & 255;                // thread id within group
    const int wg = tid2 >> 5, lane = tid2 & 31;
    const int b = p + 4 * G;
    const int len = seqlen[b];
    const float b2v = b2w[0];
    const int barid = G + 1;

    // ---- prologue (all 512 threads cooperate; converged) ----
    for (int idx = tid; idx < 32 * 256; idx += NTHREADS) {          // W1 h-cols, k rows [32r,32r+32)
        int row = idx >> 8, d = idx & 255;
        sm[OFF_W1H + idx] = W1[(size_t)(32 * r + row) * 512 + 256 + d];
    }
    for (int idx = tid; idx < 64 * 256; idx += NTHREADS) {          // Whh rows for my gates
        int q = idx >> 8, d = idx & 255;
        int gate = q >> 4, i = q & 15;
        sm[OFF_WHH + idx] = Whh[(size_t)(gate * 256 + 16 * r + i) * 256 + d];
    }
    #pragma unroll
    for (int B = 0; B < 2; B++)
        for (int idx = tid; idx < 128 * 64; idx += NTHREADS) {      // Wx[j][my 64 rows], pitch 68
            int j = idx >> 6, q = idx & 63;
            sm[OFF_WX + B * 8704 + j * 68 + q] =
                g_wx[(size_t)((p + 4 * B) * 128 + j) * 1024 + ((q >> 4) << 8) + 16 * r + (q & 15)];
        }
    if (tid < 64) {
        int gate = tid >> 4, i = tid & 15;
        int row = gate * 256 + 16 * r + i;
        sm[OFF_BIAS + tid] = bih[row] + bhh[row];
    }
    if (tid < 64) sm[OFF_HPST + tid] = 0.f;            // both groups: t=0 hproj = 0
    if (tid < 32) sm[OFF_CST + tid] = 0.f;
    if (r == 0 && tid < 2) out[SEQ_OFF + p + 4 * tid] = (float)seqlen[p + 4 * tid];

    // per-thread loop-invariant regs: (jE2 = tid2>>1, qE2 = tid2&1) -> 16 k's
    const int jE2 = tid2 >> 1, qE2 = tid2 & 1;
    float xwr[16], w2r[16];
    {
        const float* src = g_xw1 + (size_t)(b * 128 + jE2) * 512 + 32 * r + qE2 * 16;
        const float* w2s = W2 + 32 * r + qE2 * 16;
        #pragma unroll
        for (int i = 0; i < 16; i++) { xwr[i] = src[i]; w2r[i] = w2s[i]; }
    }
    __syncthreads();   // last block-wide barrier; groups diverge below

    for (int t = 0; t < TT; t++) {
        const int slot = t & 1;
        const bool active = t < len;

        // ---- h phase (t>=1): group-autonomous wait, L2 h load, hproj (4 rows/warp) ----
        float4 h0 = make_float4(0.f, 0.f, 0.f, 0.f), h1 = h0;
        if (t > 0) {
            spin16(&g_fh[b][t - 1]);
            h0 = ldcv4(&g_h[b][slot][lane * 8]);
            h1 = ldcv4(&g_h[b][slot][lane * 8 + 4]);
            #pragma unroll
            for (int rr = 0; rr < 4; rr++) {
                int row = wg * 4 + rr;
                const float* wr = sm + OFF_W1H + row * 256;
                float4 a0 = *(const float4*)(wr + lane * 8);
                float4 a1 = *(const float4*)(wr + lane * 8 + 4);
                float acc = a0.x*h0.x + a0.y*h0.y + a0.z*h0.z + a0.w*h0.w
                          + a1.x*h1.x + a1.y*h1.y + a1.z*h1.z + a1.w*h1.w;
                acc = wsum(acc);
                if (lane == 0) sm[OFF_HPST + G * 32 + row] = acc;
            }
        }
        gbar(barid);   // HPST[G] ready

        // ---- P2: energy partials (16 tanh/thread) -> g_ep ----
        {
            const float4* hp4 = (const float4*)(sm + OFF_HPST + G * 32 + qE2 * 16);
            float4 hv[4];
            #pragma unroll
            for (int m = 0; m < 4; m++) hv[m] = hp4[m];
            const float* hp = (const float*)hv;
            float acc = 0.f;
            #pragma unroll
            for (int i = 0; i < 16; i++)
                acc = fmaf(tanh_m(xwr[i] + hp[i]), w2r[i], acc);
            acc += __shfl_xor_sync(0xffffffffu, acc, 1);
            if (qE2 == 0) g_ep[b][slot][r][jE2] = acc;
        }
        gbar(barid);   // EP stores ordered before release
        if (tid2 == 0) red_rel(&g_fep[b][t]);

        // ---- hWhh (8 rows/warp) — hidden under the EP round trip ----
        #pragma unroll
        for (int rr = 0; rr < 8; rr++) {
            int row = wg * 8 + rr;
            const float* wr = sm + OFF_WHH + row * 256;
            float4 a0 = *(const float4*)(wr + lane * 8);
            float4 a1 = *(const float4*)(wr + lane * 8 + 4);
            float acc = a0.x*h0.x + a0.y*h0.y + a0.z*h0.z + a0.w*h0.w
                      + a1.x*h1.x + a1.y*h1.y + a1.z*h1.z + a1.w*h1.w;
            acc = wsum(acc);
            if (lane == 0) sm[OFF_HWST + G * 64 + row] = acc;
        }

        // ---- P3: EP wait; read 8 peers/thread; softmax ----
        spin16(&g_fep[b][t]);
        float ex = 0.f;
        {
            const float* epb = &g_ep[b][slot][0][0];
            float s = 0.f;
            #pragma unroll
            for (int i = 0; i < 8; i++)
                s += ldcv(epb + (qE2 * 8 + i) * 128 + jE2);
            s += __shfl_xor_sync(0xffffffffu, s, 1);
            if (qE2 == 0)
                ex = (jE2 < len) ? __expf(tanh_m(s + b2v)) : 0.f;  // energies in [-1,1]
        }
        float wp = wsum(ex);
        if (lane == 0) sm[OFF_SRED + G * 8 + wg] = wp;
        gbar(barid);   // SRED[G] ready (also publishes HWST[G])
        {
            const float4* sr = (const float4*)(sm + OFF_SRED + G * 8);
            float4 a = sr[0], c = sr[1];
            float S = (a.x + a.y + a.z + a.w) + (c.x + c.y + c.z + c.w);
            float Sinv = __fdividef(1.f, S);
            if (qE2 == 0) {
                float wv = active ? ex * Sinv : 0.f;
                sm[OFF_WB + G * 128 + jE2] = wv;
                if ((jE2 >> 3) == r)
                    out[ATTN_OFF + (size_t)(b * 128 + t) * 128 + jE2] = wv;
            }
        }
        gbar(barid);   // WB[G] ready

        // ---- P4: gates: row q = tid2>>2, jq = tid2&3 covers j = jq + 4*jj ----
        {
            int q = tid2 >> 2, jq = tid2 & 3;
            const float* wx = sm + OFF_WX + G * 8704 + q;
            const float* wb = sm + OFF_WB + G * 128;
            float acc = 0.f;
            #pragma unroll
            for (int jj = 0; jj < 32; jj++) {
                int j = jq + 4 * jj;
                acc = fmaf(wb[j], wx[j * 68], acc);
            }
            acc += __shfl_xor_sync(0xffffffffu, acc, 1);
            acc += __shfl_xor_sync(0xffffffffu, acc, 2);
            if (jq == 0) {
                acc += sm[OFF_HWST + G * 64 + q] + sm[OFF_BIAS + q];
                sm[OFF_GFIN + G * 64 + q] = ((q >> 4) == 2) ? tanh_m(acc) : sigmoid_m(acc);
            }
        }
        gbar(barid);   // GFIN[G] ready

        // ---- P5 (warp 0 of group): LSTM update; outputs; publish h(t+1) ----
        if (tid2 < 16) {
            const float* gf = sm + OFF_GFIN + G * 64;
            float c = gf[16 + tid2] * sm[OFF_CST + G * 16 + tid2] + gf[tid2] * gf[32 + tid2];
            sm[OFF_CST + G * 16 + tid2] = c;
            float hn = gf[48 + tid2] * tanh_m(c);
            out[(size_t)(b * 128 + t) * 256 + 16 * r + tid2] = active ? hn : 0.f;
            if (t == len - 1) out[HID_OFF + b * 256 + 16 * r + tid2] = hn;
            if (t < TT - 1) g_h[b][(t + 1) & 1][16 * r + tid2] = hn;
            __syncwarp(0x0000ffffu);
            if (tid2 == 0 && t < TT - 1) red_rel(&g_fh[b][t]);
        }
        // no trailing bar: group gates on next step's spins
    }
}

// ---------------- host launch ----------------
extern "C" void kernel_launch(void* const* d_in, const int* in_sizes, int n_in,
                              void* d_out, int out_size) {
    const float* x   = (const float*)d_in[0];
    const int*   sl  = (const int*)  d_in[1];
    const float* W1  = (const float*)d_in[2];
    const float* b1  = (const float*)d_in[3];
    const float* W2  = (const float*)d_in[4];
    const float* b2  = (const float*)d_in[5];
    const float* Wih = (const float*)d_in[6];
    const float* Whh = (const float*)d_in[7];
    const float* bih = (const float*)d_in[8];
    const float* bhh = (const float*)d_in[9];
    float* out = (float*)d_out;

    zero_flags<<<2, 512>>>();
    xw1_gemm<<<dim3(16, 8), dim3(16, 16)>>>(x, W1, b1);
    {
        float* gwx;
        cudaGetSymbolAddress((void**)&gwx, g_wx);
        nt_gemm<1024, false><<<dim3(16, 16), dim3(16, 16)>>>(x, Wih, nullptr, gwx);
    }

    cudaFuncSetAttribute(lstm_attn, cudaFuncAttributeMaxDynamicSharedMemorySize, SMEM_BYTES);
    lstm_attn<<<64, NTHREADS, SMEM_BYTES>>>(x, sl, W1, W2, b2, Whh, bih, bhh, out);
}